// round 7
// baseline (speedup 1.0000x reference)
#include <cuda_runtime.h>
#include <cstdint>

#define BB 32
#define JJ 256
#define MM 128
#define DD 200
#define NTH 512
#define CH 50            // d-chunk per rank
#define CSZ 4            // cluster size
#define MP 53            // padded mem row stride (conflict-free column walks)
#define MEMLN 13568      // per-lane mem floats (2 banks * 128 * MP)
#define MEMBK 6784       // per-bank floats (128 * MP)

// ---------------- persistent transposed weight scratch (fp32) ----------------
__device__ __align__(16) float g_wTg[400 * 800];   // [k][4*d+g], k<200 ih else hh
__device__ __align__(16) float g_wTfc1[400 * 200]; // [k][d], k: x then q
__device__ __align__(16) float g_wTfc[200 * 200];  // [k][d]
__device__ __align__(16) float g_bg[800];          // b_ih+b_hh gate-interleaved

__global__ void prep_kernel(const float* __restrict__ w_fc, const float* __restrict__ w_fc1,
                            const float* __restrict__ w_ih, const float* __restrict__ w_hh,
                            const float* __restrict__ b_ih, const float* __restrict__ b_hh)
{
    int stride = gridDim.x * blockDim.x;
    int i0 = blockIdx.x * blockDim.x + threadIdx.x;

    for (int idx = i0; idx < 400 * 800; idx += stride) {
        int k = idx / 800, rem = idx % 800;
        int d = rem >> 2, g = rem & 3;
        int o = g * 200 + d;
        g_wTg[idx] = (k < 200) ? w_ih[o * 200 + k] : w_hh[o * 200 + (k - 200)];
    }
    for (int idx = i0; idx < 800; idx += stride) {
        int d = idx >> 2, g = idx & 3;
        int o = g * 200 + d;
        g_bg[idx] = b_ih[o] + b_hh[o];
    }
    for (int idx = i0; idx < 400 * 200; idx += stride) {
        int k = idx / 200, d = idx % 200;
        g_wTfc1[idx] = w_fc1[d * 400 + k];
    }
    for (int idx = i0; idx < 200 * 200; idx += stride) {
        int k = idx / 200, d = idx % 200;
        g_wTfc[idx] = w_fc[d * 200 + k];
    }
}

__device__ __forceinline__ float sigf(float v) { return 1.0f / (1.0f + __expf(-v)); }
__device__ __forceinline__ float ftanh(float x) { return 1.0f - 2.0f / (__expf(2.0f * x) + 1.0f); }

__device__ __forceinline__ void cluster_bar()
{
    asm volatile("barrier.cluster.arrive.aligned;\n\t"
                 "barrier.cluster.wait.aligned;" ::: "memory");
}
__device__ __forceinline__ void st_peer(uint32_t laddr, uint32_t peer, float v)
{
    uint32_t r;
    asm volatile("mapa.shared::cluster.u32 %0, %1, %2;" : "=r"(r) : "r"(laddr), "r"(peer));
    asm volatile("st.shared::cluster.f32 [%0], %1;" :: "r"(r), "f"(v) : "memory");
}
__device__ __forceinline__ void st_peer_v4(uint32_t laddr, uint32_t peer, float4 v)
{
    uint32_t r;
    unsigned long long lo = (unsigned long long)__float_as_uint(v.x) |
                            ((unsigned long long)__float_as_uint(v.y) << 32);
    unsigned long long hi = (unsigned long long)__float_as_uint(v.z) |
                            ((unsigned long long)__float_as_uint(v.w) << 32);
    asm volatile("mapa.shared::cluster.u32 %0, %1, %2;" : "=r"(r) : "r"(laddr), "r"(peer));
    asm volatile("st.shared::cluster.b64 [%0], %1;" :: "r"(r), "l"(lo) : "memory");
    asm volatile("st.shared::cluster.b64 [%0+8], %1;" :: "r"(r), "l"(hi) : "memory");
}

// ---------------- SMEM layout (float indices), 2 lanes ----------------
#define SM_MEM   0                       // mem[2 ln][2 bank][128][MP] = 27136
#define SM_GP    27136                   // gparts[ln][4][200] = 1600
#define SM_ATTP  28736                   // attp[ln][4][128] = 1024
#define SM_QP    29760                   // qparts[ln][4][50] = 400
#define SM_ZP    30160                   // zparts[ln][4][50] = 400
#define SM_PART  30560                   // part[ln][1600] = 3200
#define SM_ATT   33760                   // att[ln][128] = 256
#define SM_RED   34016                   // red[ln][8] = 16
#define SM_XV    34032                   // xv[ln][56] = 112
#define SM_CS    34144                   // cstage[buf][ln][128] = 512
#define SM_BJ    34656                   // bstage[buf][ln][200] = 800
#define SM_QL    35456                   // qloc[ln][56] = 112
#define SM_HL    35568                   // hloc[ln][56] = 112
#define SM_CV    35680                   // cvec[ln][56] = 112
#define SM_BG    35792                   // bgs[224]
#define SM_BFC   36016                   // bfcs[56]
#define SM_BFC1  36072                   // bfc1s[56]
#define SM_TOT   36128                   // 144512 bytes

__global__ void __launch_bounds__(NTH, 1) __cluster_dims__(CSZ, 1, 1)
speaker_kernel(const float* __restrict__ cosp, const float* __restrict__ bank,
               const float* __restrict__ mem_a, const float* __restrict__ mem_b,
               const float* __restrict__ b_fc, const float* __restrict__ b_fc1,
               float* __restrict__ out)
{
    extern __shared__ float sm[];
    float* bgs   = sm + SM_BG;
    float* bfcs  = sm + SM_BFC;
    float* bfc1s = sm + SM_BFC1;

    const int tid  = threadIdx.x;
    const int lane0 = (blockIdx.x >> 2) * 2;  // this cluster's first batch lane
    const uint32_t rank = blockIdx.x & 3;
    const int cbase = (int)rank * CH;
    const uint32_t sb = (uint32_t)__cvta_generic_to_shared(sm);

    // ---- init: biases, mem chunks (both lanes), first-step staging ----
    if (tid < 224) bgs[tid] = g_bg[rank * 200 + min(tid, 199)];
    if (tid < CH) { bfcs[tid] = b_fc[cbase + tid]; bfc1s[tid] = b_fc1[cbase + tid]; }
    for (int idx = tid; idx < 2 * MM * CH; idx += NTH) {
        int ln = idx / (MM * CH), r2 = idx % (MM * CH);
        int m = r2 / CH, d = r2 % CH;
        sm[SM_MEM + ln * MEMLN + m * MP + d] =
            mem_a[(lane0 + ln) * MM * DD + m * DD + cbase + d];
        sm[SM_MEM + ln * MEMLN + MEMBK + m * MP + d] =
            mem_b[(lane0 + ln) * MM * DD + m * DD + cbase + d];
    }
    for (int i = tid; i < 2 * MM; i += NTH) {
        int ln = i >> 7, t = i & 127;
        sm[SM_CS + ln * 128 + t] = cosp[((lane0 + ln) * JJ + 0) * MM + t];
    }
    for (int i = tid; i < 2 * DD; i += NTH) {
        int ln = i / DD, t = i % DD;
        sm[SM_BJ + ln * 200 + t] = bank[(0 * BB + lane0 + ln) * DD + t];
    }
    __syncthreads();
    cluster_bar();

    for (int j = 0; j < JJ; ++j) {
        const int flag = j & 1;
        const int slot = j >> 1;
        const int jb = j & 1;       // staging buffer
        float* mem0 = sm + SM_MEM + flag * MEMBK;
        float* mem1 = sm + SM_MEM + MEMLN + flag * MEMBK;
        const float* cs0 = sm + SM_CS + jb * 256;
        const float* cs1 = cs0 + 128;
        const float* bj0 = sm + SM_BJ + jb * 400;
        const float* bj1 = bj0 + 200;

        // ---- P1: q-init GEMV, dual-lane fused (8 ks x 50 c, 25 iters) ----
        if (tid < 400) {
            int ks = tid / 50, c = tid % 50;
            int k0 = ks * 25;
            const float* W = g_wTfc + cbase + c;
            float a0 = 0.f, a1 = 0.f;
            #pragma unroll 5
            for (int i = 0; i < 25; ++i) {
                float w = W[(k0 + i) * 200];
                a0 += bj0[k0 + i] * w;
                a1 += bj1[k0 + i] * w;
            }
            sm[SM_PART + ks * 50 + c] = a0;
            sm[SM_PART + 1600 + ks * 50 + c] = a1;
        }
        __syncthreads();
        // ---- P2: h-init partials (4 segs x 50, 32 iters, per-lane warps) + q combine ----
        {
            int r = tid & 255;
            if (r < 200 && tid < 456) {
                int ln = tid >> 8;
                int seg = r / 50, d = r % 50;
                const float* mp = (ln ? mem1 : mem0) + (seg * 32) * MP + d;
                const float* cj = ln ? cs1 : cs0;
                float a = 0.f;
                #pragma unroll 8
                for (int m = 0; m < 32; ++m) a += cj[seg * 32 + m] * mp[m * MP];
                sm[SM_PART + ln * 1600 + 400 + seg * 50 + d] = a;
            } else if (r >= 200 && r < 250) {   // lane0: tid 200-249, lane1: tid 456-505
                int ln = tid >> 8, t = r - 200;
                float a = bfcs[t];
                #pragma unroll
                for (int ks = 0; ks < 8; ++ks) a += sm[SM_PART + ln * 1600 + ks * 50 + t];
                sm[SM_QL + ln * 56 + t] = a;
                sm[SM_CV + ln * 56 + t] = 0.0f;
            }
        }
        __syncthreads();
        // ---- P3: h combine ----
        {
            int r = tid & 255;
            if (r < CH && tid < 306) {
                int ln = tid >> 8;
                float* pp = sm + SM_PART + ln * 1600 + 400;
                sm[SM_HL + ln * 56 + r] = pp[r] + pp[50 + r] + pp[100 + r] + pp[150 + r];
            }
        }
        __syncthreads();

        // ---------------- inner loop P=3 ----------------
        for (int p = 0; p < 3; ++p) {
            // G0: gates GEMV dual-lane fused; idle threads prefetch next stage
            if (tid < 400) {
                int ks = tid / 200, c = tid % 200;
                const float4* W4 = reinterpret_cast<const float4*>(g_wTg)
                                   + (ks ? (200 + cbase) : cbase) * 200 + c;
                const float* a0p = sm + (ks ? SM_HL : SM_QL);
                const float* a1p = a0p + 56;
                float4 s0 = make_float4(0.f, 0.f, 0.f, 0.f);
                float4 s1 = make_float4(0.f, 0.f, 0.f, 0.f);
                #pragma unroll 10
                for (int i = 0; i < CH; ++i) {
                    float4 w = W4[i * 200];
                    float v0 = a0p[i], v1 = a1p[i];
                    s0.x += v0 * w.x; s0.y += v0 * w.y; s0.z += v0 * w.z; s0.w += v0 * w.w;
                    s1.x += v1 * w.x; s1.y += v1 * w.y; s1.z += v1 * w.z; s1.w += v1 * w.w;
                }
                reinterpret_cast<float4*>(sm + SM_PART)[ks * 200 + c] = s0;
                reinterpret_cast<float4*>(sm + SM_PART + 1600)[ks * 200 + c] = s1;
            } else if (p == 0 && j + 1 < JJ) {
                int nj = j + 1, nb = nj & 1, t = tid - 400;
                for (int i = t; i < MM; i += 112) {
                    sm[SM_CS + nb * 256 + i]       = cosp[(lane0 * JJ + nj) * MM + i];
                    sm[SM_CS + nb * 256 + 128 + i] = cosp[((lane0 + 1) * JJ + nj) * MM + i];
                }
                for (int i = t; i < DD; i += 112) {
                    sm[SM_BJ + nb * 400 + i]       = bank[(nj * BB + lane0) * DD + i];
                    sm[SM_BJ + nb * 400 + 200 + i] = bank[(nj * BB + lane0 + 1) * DD + i];
                }
            }
            __syncthreads();
            // G0b: combine ks + deposit quad to owner (both lanes, disjoint warps)
            {
                int r = tid & 255;
                if (r < 200 && tid < 456) {
                    int ln = tid >> 8;
                    const float4* p4 = reinterpret_cast<const float4*>(sm + SM_PART + ln * 1600);
                    float4 a = p4[r], b = p4[200 + r];
                    float4 v = make_float4(a.x + b.x, a.y + b.y, a.z + b.z, a.w + b.w);
                    int owner = r / CH, cq = r % CH;
                    uint32_t off = SM_GP + ln * 800 + rank * 200 + cq * 4;
                    if (owner == (int)rank) *reinterpret_cast<float4*>(sm + off) = v;
                    else st_peer_v4(sb + 4u * off, (uint32_t)owner, v);
                }
            }
            cluster_bar();   // Bg
            // G1: reduce 4 sources + LSTM (lane0: warps 0-6, lane1: warps 8-14)
            {
                bool grp0 = (tid < 224), grp1 = (tid >= 256 && tid < 480);
                if (grp0 || grp1) {
                    int ln = grp1 ? 1 : 0;
                    int t = min((tid & 255), 199);
                    int chl = t >> 2, gi = t & 3;
                    const float* gp = sm + SM_GP + ln * 800;
                    float g = bgs[t];
                    #pragma unroll
                    for (int s = 0; s < 4; ++s) g += gp[s * 200 + chl * 4 + gi];
                    float val = (gi == 2) ? ftanh(g) : sigf(g);
                    float ig = __shfl_sync(0xffffffffu, val, 0, 4);
                    float fg = __shfl_sync(0xffffffffu, val, 1, 4);
                    float gg = __shfl_sync(0xffffffffu, val, 2, 4);
                    float og = __shfl_sync(0xffffffffu, val, 3, 4);
                    if ((tid & 255) < 200 && gi == 0) {
                        float cc = fg * sm[SM_CV + ln * 56 + chl] + ig * gg;
                        sm[SM_CV + ln * 56 + chl] = cc;
                        sm[SM_HL + ln * 56 + chl] = og * ftanh(cc);
                    }
                }
            }
            __syncthreads();
            // G2: attention logit partials over local d-chunk (both lanes, 512 threads)
            {
                int ln = tid >> 8, r = tid & 255;
                int m = r & 127, hf = r >> 7;
                const float* mrow = (ln ? mem1 : mem0) + m * MP + hf * 25;
                const float* hseg = sm + SM_HL + ln * 56 + hf * 25;
                float a = 0.f;
                #pragma unroll 5
                for (int i = 0; i < 25; ++i) a += hseg[i] * mrow[i];
                sm[SM_PART + ln * 1600 + hf * 128 + m] = a;
            }
            __syncthreads();
            // G2b: push logit partials to all peers (both lanes)
            {
                int r = tid & 255;
                if (r < 128 && tid < 384) {
                    int ln = tid >> 8;
                    const float* pp = sm + SM_PART + ln * 1600;
                    float a = pp[r] + pp[128 + r];
                    uint32_t off = SM_ATTP + ln * 512 + rank * 128 + r;
                    sm[off] = a;
                    #pragma unroll
                    for (uint32_t pr = 1; pr < CSZ; ++pr)
                        st_peer(sb + 4u * off, (rank + pr) & 3, a);
                }
            }
            cluster_bar();   // Ba
            // G3: single-warp softmax per lane (warp 0 = lane0, warp 8 = lane1)
            if (tid < 32 || (tid >= 256 && tid < 288)) {
                int ln = tid >> 8, t = tid & 31;
                const float* ap = sm + SM_ATTP + ln * 512;
                float v0 = ap[t]      + ap[128 + t]      + ap[256 + t]      + ap[384 + t];
                float v1 = ap[32 + t] + ap[160 + t]      + ap[288 + t]      + ap[416 + t];
                float v2 = ap[64 + t] + ap[192 + t]      + ap[320 + t]      + ap[448 + t];
                float v3 = ap[96 + t] + ap[224 + t]      + ap[352 + t]      + ap[480 + t];
                float mx = fmaxf(fmaxf(v0, v1), fmaxf(v2, v3));
                #pragma unroll
                for (int o = 16; o > 0; o >>= 1) mx = fmaxf(mx, __shfl_xor_sync(0xffffffffu, mx, o));
                float e0 = __expf(v0 - mx), e1 = __expf(v1 - mx);
                float e2 = __expf(v2 - mx), e3 = __expf(v3 - mx);
                float s = e0 + e1 + e2 + e3;
                #pragma unroll
                for (int o = 16; o > 0; o >>= 1) s += __shfl_xor_sync(0xffffffffu, s, o);
                float* at = sm + SM_ATT + ln * 128;
                at[t] = e0; at[32 + t] = e1; at[64 + t] = e2; at[96 + t] = e3;
                if (t == 0) sm[SM_RED + ln * 8] = 1.0f / s;
            }
            __syncthreads();
            // G5: x chunk partials (4 m-segs x 50 d, 32 iters, per-lane warps)
            {
                int r = tid & 255;
                if (r < 200 && tid < 456) {
                    int ln = tid >> 8;
                    int seg = r / 50, d = r % 50;
                    const float* mp = (ln ? mem1 : mem0) + (seg * 32) * MP + d;
                    const float* at = sm + SM_ATT + ln * 128 + seg * 32;
                    float a = 0.f;
                    #pragma unroll 8
                    for (int m = 0; m < 32; ++m) a += at[m] * mp[m * MP];
                    sm[SM_PART + ln * 1600 + seg * 50 + d] = a;
                }
            }
            __syncthreads();
            {
                int r = tid & 255;
                if (r < CH && tid < 306) {
                    int ln = tid >> 8;
                    const float* pp = sm + SM_PART + ln * 1600;
                    sm[SM_XV + ln * 56 + r] =
                        (pp[r] + pp[50 + r] + pp[100 + r] + pp[150 + r]) * sm[SM_RED + ln * 8];
                }
            }
            __syncthreads();
            // G6: fc1 GEMV dual-lane fused
            if (tid < 400) {
                int ks = tid / 200, c = tid % 200;
                const float* W = g_wTfc1 + (ks ? (200 + cbase) : cbase) * 200 + c;
                const float* a0p = sm + (ks ? SM_QL : SM_XV);
                const float* a1p = a0p + 56;
                float a0 = 0.f, a1 = 0.f;
                #pragma unroll 10
                for (int i = 0; i < CH; ++i) {
                    float w = W[i * 200];
                    a0 += a0p[i] * w;
                    a1 += a1p[i] * w;
                }
                sm[SM_PART + ks * 200 + c] = a0;
                sm[SM_PART + 1600 + ks * 200 + c] = a1;
            }
            __syncthreads();
            // G6b: deposit q partials to owner (both lanes)
            {
                int r = tid & 255;
                if (r < 200 && tid < 456) {
                    int ln = tid >> 8;
                    const float* pp = sm + SM_PART + ln * 1600;
                    float v = pp[r] + pp[200 + r];
                    int owner = r / CH;
                    uint32_t off = SM_QP + ln * 200 + rank * CH + (r % CH);
                    if (owner == (int)rank) sm[off] = v;
                    else st_peer(sb + 4u * off, (uint32_t)owner, v);
                }
            }
            cluster_bar();   // Bq
            // G7: q chunk reduce (both lanes)
            {
                int r = tid & 255;
                if (r < CH && tid < 306) {
                    int ln = tid >> 8;
                    const float* qp = sm + SM_QP + ln * 200;
                    float a = bfc1s[r];
                    #pragma unroll
                    for (int s = 0; s < 4; ++s) a += qp[s * CH + r];
                    sm[SM_QL + ln * 56 + r] = a;
                }
            }
            __syncthreads();
        }

        // ---- epilogue: z GEMV dual-lane fused + out write ----
        if (tid < 400) {
            int ks = tid / 200, c = tid % 200;
            const float* W = g_wTfc + (cbase + ks * 25) * 200 + c;
            const float* q0 = sm + SM_QL + ks * 25;
            const float* q1 = q0 + 56;
            const float* s0 = mem0 + slot * MP + ks * 25;
            const float* s1 = mem1 + slot * MP + ks * 25;
            float a0 = 0.f, a1 = 0.f;
            #pragma unroll 5
            for (int i = 0; i < 25; ++i) {
                float w = W[i * 200];
                a0 += (q0[i] + s0[i]) * w;
                a1 += (q1[i] + s1[i]) * w;
            }
            sm[SM_PART + ks * 200 + c] = a0;
            sm[SM_PART + 1600 + ks * 200 + c] = a1;
        } else if (tid >= 400 && tid < 500) {
            int ln = (tid - 400) / CH, t = (tid - 400) % CH;
            out[((lane0 + ln) * JJ + j) * DD + cbase + t] = sm[SM_QL + ln * 56 + t];
        }
        __syncthreads();
        {
            int r = tid & 255;
            if (r < 200 && tid < 456) {
                int ln = tid >> 8;
                const float* pp = sm + SM_PART + ln * 1600;
                float v = pp[r] + pp[200 + r];
                int owner = r / CH;
                uint32_t off = SM_ZP + ln * 200 + rank * CH + (r % CH);
                if (owner == (int)rank) sm[off] = v;
                else st_peer(sb + 4u * off, (uint32_t)owner, v);
            }
        }
        cluster_bar();   // Bz
        {
            int r = tid & 255;
            if (r < CH && tid < 306) {
                int ln = tid >> 8;
                const float* zp = sm + SM_ZP + ln * 200;
                float a = 2.0f * bfcs[r];
                #pragma unroll
                for (int s = 0; s < 4; ++s) a += zp[s * CH + r];
                float z = tanhf(a);
                float* mslot = (ln ? mem1 : mem0) + slot * MP;
                mslot[r] *= z;
            }
        }
        __syncthreads();
    }
}

extern "C" void kernel_launch(void* const* d_in, const int* in_sizes, int n_in,
                              void* d_out, int out_size)
{
    const float* cosp  = (const float*)d_in[0];
    const float* bank  = (const float*)d_in[1];
    const float* mem_a = (const float*)d_in[2];
    const float* mem_b = (const float*)d_in[3];
    const float* w_fc  = (const float*)d_in[4];
    const float* b_fc  = (const float*)d_in[5];
    const float* w_fc1 = (const float*)d_in[6];
    const float* b_fc1 = (const float*)d_in[7];
    const float* w_ih  = (const float*)d_in[8];
    const float* w_hh  = (const float*)d_in[9];
    const float* b_ih  = (const float*)d_in[10];
    const float* b_hh  = (const float*)d_in[11];
    float* out = (float*)d_out;

    prep_kernel<<<148, 256>>>(w_fc, w_fc1, w_ih, w_hh, b_ih, b_hh);

    size_t smem_bytes = SM_TOT * sizeof(float);
    cudaFuncSetAttribute(speaker_kernel, cudaFuncAttributeMaxDynamicSharedMemorySize,
                         (int)smem_bytes);
    speaker_kernel<<<(BB / 2) * CSZ, NTH, smem_bytes>>>(cosp, bank, mem_a, mem_b,
                                                        b_fc, b_fc1, out);
}